// round 1
// baseline (speedup 1.0000x reference)
#include <cuda_runtime.h>
#include <math.h>

#define TSTEPS 512
#define BATCH  64
#define DIN    256
#define HID    512
#define DOUT   256
#define G4H    2048
#define NBLK   128

typedef unsigned long long ull;

// ---------------- scratch (module-scope __device__ arrays: no allocation) ----------------
__device__ float d_Genc[(size_t)TSTEPS * G4H * BATCH];    // [t][gate*H+u][b]  (268 MB)
__device__ float d_Gdec[(size_t)TSTEPS * G4H * BATCH];    // (268 MB)
__device__ float d_hbuf[2][HID * BATCH];                  // packed pairs: [(u>>1)*B + b]*2 + (u&1)
__device__ float d_cbuf[HID * BATCH];                     // [u][b]
__device__ float d_hs[(size_t)TSTEPS * HID * BATCH];      // [t][u][b]   (64 MB)
__device__ float d_logits[(size_t)TSTEPS * BATCH * DOUT]; // [t][b][n]   (32 MB)
__device__ unsigned g_count;
__device__ volatile unsigned g_gen;

// ---------------- f32x2 helpers ----------------
__device__ __forceinline__ void fma2(ull& a, ull x, ull y) {
    asm("fma.rn.f32x2 %0, %1, %2, %3;" : "=l"(a) : "l"(x), "l"(y), "l"(a));
}
__device__ __forceinline__ ull pack2(float lo, float hi) {
    ull r; asm("mov.b64 %0, {%1, %2};" : "=l"(r) : "f"(lo), "f"(hi)); return r;
}
__device__ __forceinline__ float sum2(ull v) {
    float lo, hi; asm("mov.b64 {%0, %1}, %2;" : "=f"(lo), "=f"(hi) : "l"(v));
    return lo + hi;
}
__device__ __forceinline__ float sigmoidf_(float x) { return 1.0f / (1.0f + expf(-x)); }

// ---------------- init: pack initial h (pair-interleaved) and c ----------------
__global__ __launch_bounds__(256) void init_state(const float* __restrict__ h0,
                                                  const float* __restrict__ c0) {
    int i = blockIdx.x * blockDim.x + threadIdx.x;   // 0..32767
    if (i >= HID * BATCH) return;
    int b = i >> 9;           // h0 layout [1][B][H] -> element (b,u) at b*H+u
    int u = i & 511;
    d_hbuf[0][((u >> 1) * BATCH + b) * 2 + (u & 1)] = h0[i];
    d_cbuf[u * BATCH + b] = c0[i];
}

// ---------------- input projection GEMM: G[t][n][b] = sum_k W[n][k]*X[t'][b][k] + bias[n] ----
// which = 0: enc (X = x, t' = t);  which = 1: dec (X = target, t' = t-1; t==0 -> zeros)
__global__ __launch_bounds__(256) void proj_kernel(const float* __restrict__ X,
                                                   const float* __restrict__ W,
                                                   const float* __restrict__ bias,
                                                   int which) {
    __shared__ ull   Ws2[64][33];   // duplicated (w,w) pairs
    __shared__ float Xs[32][68];    // [k][b], padded (row stride 272B, 16B aligned)

    float* __restrict__ Gout = which ? d_Gdec : d_Genc;
    int t  = blockIdx.y;
    int n0 = blockIdx.x * 64;
    int tid = threadIdx.x;
    int tx = tid & 15, ty = tid >> 4;           // tx -> 4 b's, ty -> 4 n's
    bool zero_x = (which && t == 0);
    const float* Xt = X + ((size_t)(t - which) * BATCH) * DIN;

    ull acc[4][2];
#pragma unroll
    for (int j = 0; j < 4; j++) { acc[j][0] = 0ull; acc[j][1] = 0ull; }

    int ldn = tid >> 2;               // 0..63
    int ldk = (tid & 3) * 8;          // 0,8,16,24

    for (int k0 = 0; k0 < DIN; k0 += 32) {
        // weights: 64 rows x 32 k, duplicated into ull pairs
        {
            const float4* src = (const float4*)(W + (size_t)(n0 + ldn) * DIN + k0 + ldk);
            float4 a = src[0], c = src[1];
            Ws2[ldn][ldk + 0] = pack2(a.x, a.x);
            Ws2[ldn][ldk + 1] = pack2(a.y, a.y);
            Ws2[ldn][ldk + 2] = pack2(a.z, a.z);
            Ws2[ldn][ldk + 3] = pack2(a.w, a.w);
            Ws2[ldn][ldk + 4] = pack2(c.x, c.x);
            Ws2[ldn][ldk + 5] = pack2(c.y, c.y);
            Ws2[ldn][ldk + 6] = pack2(c.z, c.z);
            Ws2[ldn][ldk + 7] = pack2(c.w, c.w);
        }
        // activations: transpose-load X[t'][b][k] -> Xs[k][b]
        if (zero_x) {
#pragma unroll
            for (int i = 0; i < 8; i++) Xs[ldk + i][ldn] = 0.0f;
        } else {
            const float4* src = (const float4*)(Xt + (size_t)ldn * DIN + k0 + ldk);
            float4 a = src[0], c = src[1];
            Xs[ldk + 0][ldn] = a.x; Xs[ldk + 1][ldn] = a.y;
            Xs[ldk + 2][ldn] = a.z; Xs[ldk + 3][ldn] = a.w;
            Xs[ldk + 4][ldn] = c.x; Xs[ldk + 5][ldn] = c.y;
            Xs[ldk + 6][ldn] = c.z; Xs[ldk + 7][ldn] = c.w;
        }
        __syncthreads();
#pragma unroll 8
        for (int k = 0; k < 32; k++) {
            ull xa = *(const ull*)&Xs[k][tx * 4];
            ull xb = *(const ull*)&Xs[k][tx * 4 + 2];
            ull w0 = Ws2[ty * 4 + 0][k];
            ull w1 = Ws2[ty * 4 + 1][k];
            ull w2 = Ws2[ty * 4 + 2][k];
            ull w3 = Ws2[ty * 4 + 3][k];
            fma2(acc[0][0], w0, xa); fma2(acc[0][1], w0, xb);
            fma2(acc[1][0], w1, xa); fma2(acc[1][1], w1, xb);
            fma2(acc[2][0], w2, xa); fma2(acc[2][1], w2, xb);
            fma2(acc[3][0], w3, xa); fma2(acc[3][1], w3, xb);
        }
        __syncthreads();
    }
#pragma unroll
    for (int j = 0; j < 4; j++) {
        int n = n0 + ty * 4 + j;
        float bb = bias[n];
        float l0, l1, l2, l3;
        asm("mov.b64 {%0, %1}, %2;" : "=f"(l0), "=f"(l1) : "l"(acc[j][0]));
        asm("mov.b64 {%0, %1}, %2;" : "=f"(l2), "=f"(l3) : "l"(acc[j][1]));
        float4 o = make_float4(l0 + bb, l1 + bb, l2 + bb, l3 + bb);
        *(float4*)(Gout + ((size_t)t * G4H + n) * BATCH + tx * 4) = o;
    }
}

// ---------------- software grid barrier (all NBLK blocks co-resident) ----------------
__device__ __forceinline__ void grid_sync() {
    __syncthreads();
    if (threadIdx.x == 0) {
        __threadfence();
        unsigned target = g_gen + 1;          // read BEFORE arriving
        unsigned a = atomicAdd(&g_count, 1u);
        if (a == NBLK - 1) {
            atomicExch(&g_count, 0u);
            __threadfence();
            g_gen = target;
        } else {
            while (g_gen != target) { }
        }
        __threadfence();
    }
    __syncthreads();
}

// ---------------- persistent recurrent LSTM kernel ----------------
// which = 0: encoder (reads d_Genc, no hs); which = 1: decoder (reads d_Gdec, writes d_hs)
__global__ __launch_bounds__(256) void recur_kernel(const float* __restrict__ Whh, int which) {
    extern __shared__ ull sm[];
    ull* w2 = sm;                 // [16 rows][256 pairs]  (32 KB)
    ull* h2 = sm + 16 * 256;      // [256 pairs][64 b]     (128 KB)

    const float* __restrict__ G = which ? d_Gdec : d_Genc;
    int tid = threadIdx.x;
    int b = tid & 63, ul = tid >> 6;
    int u0 = blockIdx.x * 4;
    int u = u0 + ul;

    // load this block's 16 Whh rows (4 units x 4 gates) as f32x2 pairs
    for (int idx = tid; idx < 16 * 256; idx += 256) {
        int r = idx >> 8, kk = idx & 255;
        int g = r >> 2, uu = r & 3;
        const float* wr = Whh + ((size_t)(g * HID + u0 + uu)) * HID + kk * 2;
        w2[idx] = *(const ull*)wr;
    }

    float c = d_cbuf[u * BATCH + b];
    const ulonglong2* wi2 = (const ulonglong2*)(w2 + (0 * 4 + ul) * 256);
    const ulonglong2* wf2 = (const ulonglong2*)(w2 + (1 * 4 + ul) * 256);
    const ulonglong2* wg2 = (const ulonglong2*)(w2 + (2 * 4 + ul) * 256);
    const ulonglong2* wo2 = (const ulonglong2*)(w2 + (3 * 4 + ul) * 256);

    for (int t = 0; t < TSTEPS; t++) {
        grid_sync();                                     // previous step's h is published
        // stage h (128 KB) into smem
        const float4* src = (const float4*)d_hbuf[t & 1];
        float4* dst = (float4*)h2;
#pragma unroll
        for (int i = 0; i < 32; i++) dst[tid + i * 256] = src[tid + i * 256];
        // prefetch this thread's 4 precomputed gate inputs (x-proj + bias)
        size_t gb = ((size_t)t * G4H + u) * BATCH + b;
        float pi = G[gb];
        float pf = G[gb + (size_t)512 * BATCH];
        float pg = G[gb + (size_t)1024 * BATCH];
        float po = G[gb + (size_t)1536 * BATCH];
        __syncthreads();

        ull ai = 0ull, af = 0ull, ag = 0ull, ao = 0ull;
        const ull* hp = h2 + b;
#pragma unroll 4
        for (int kk2 = 0; kk2 < 128; kk2++) {
            ull h0v = hp[kk2 * 128];
            ull h1v = hp[kk2 * 128 + 64];
            ulonglong2 wiv = wi2[kk2], wfv = wf2[kk2], wgv = wg2[kk2], wov = wo2[kk2];
            fma2(ai, wiv.x, h0v); fma2(ai, wiv.y, h1v);
            fma2(af, wfv.x, h0v); fma2(af, wfv.y, h1v);
            fma2(ag, wgv.x, h0v); fma2(ag, wgv.y, h1v);
            fma2(ao, wov.x, h0v); fma2(ao, wov.y, h1v);
        }
        float gi = sum2(ai) + pi;
        float gf = sum2(af) + pf;
        float gg = sum2(ag) + pg;
        float go = sum2(ao) + po;
        float iv = sigmoidf_(gi);
        float fv = sigmoidf_(gf);
        float gv = tanhf(gg);
        float ov = sigmoidf_(go);
        c = fv * c + iv * gv;
        float h = ov * tanhf(c);

        float* ho = d_hbuf[(t + 1) & 1];
        ho[((u >> 1) * BATCH + b) * 2 + (u & 1)] = h;
        if (which) d_hs[((size_t)t * HID + u) * BATCH + b] = h;
    }
    d_cbuf[u * BATCH + b] = c;   // hand c to the decoder kernel
}

// ---------------- FC: logits[t][b][n] = hs[t][b][:] . fcW[n][:] + fcb[n] ----------------
__global__ __launch_bounds__(256) void fc_kernel(const float* __restrict__ fcW,
                                                 const float* __restrict__ fcb) {
    __shared__ ull   Ws2[64][33];
    __shared__ float Hs[32][68];

    int t  = blockIdx.y;
    int n0 = blockIdx.x * 64;
    int tid = threadIdx.x;
    int tx = tid & 15, ty = tid >> 4;

    ull acc[4][2];
#pragma unroll
    for (int j = 0; j < 4; j++) { acc[j][0] = 0ull; acc[j][1] = 0ull; }

    int ldn = tid >> 2;
    int ldk = (tid & 3) * 8;

    for (int k0 = 0; k0 < HID; k0 += 32) {
        {
            const float4* src = (const float4*)(fcW + (size_t)(n0 + ldn) * HID + k0 + ldk);
            float4 a = src[0], c = src[1];
            Ws2[ldn][ldk + 0] = pack2(a.x, a.x);
            Ws2[ldn][ldk + 1] = pack2(a.y, a.y);
            Ws2[ldn][ldk + 2] = pack2(a.z, a.z);
            Ws2[ldn][ldk + 3] = pack2(a.w, a.w);
            Ws2[ldn][ldk + 4] = pack2(c.x, c.x);
            Ws2[ldn][ldk + 5] = pack2(c.y, c.y);
            Ws2[ldn][ldk + 6] = pack2(c.z, c.z);
            Ws2[ldn][ldk + 7] = pack2(c.w, c.w);
        }
        {
            // hs is already [t][k][b]: straight copy of a 32x64 chunk
            const float4* src = (const float4*)(d_hs + ((size_t)t * HID + k0) * BATCH);
#pragma unroll
            for (int i = 0; i < 2; i++) {
                int fi = tid * 2 + i;                 // float4 index within 2048 floats
                float4 v = src[fi];
                int k = fi >> 4, cb = (fi & 15) * 4;
                Hs[k][cb + 0] = v.x; Hs[k][cb + 1] = v.y;
                Hs[k][cb + 2] = v.z; Hs[k][cb + 3] = v.w;
            }
        }
        __syncthreads();
#pragma unroll 8
        for (int k = 0; k < 32; k++) {
            ull xa = *(const ull*)&Hs[k][tx * 4];
            ull xb = *(const ull*)&Hs[k][tx * 4 + 2];
            ull w0 = Ws2[ty * 4 + 0][k];
            ull w1 = Ws2[ty * 4 + 1][k];
            ull w2v = Ws2[ty * 4 + 2][k];
            ull w3 = Ws2[ty * 4 + 3][k];
            fma2(acc[0][0], w0, xa);  fma2(acc[0][1], w0, xb);
            fma2(acc[1][0], w1, xa);  fma2(acc[1][1], w1, xb);
            fma2(acc[2][0], w2v, xa); fma2(acc[2][1], w2v, xb);
            fma2(acc[3][0], w3, xa);  fma2(acc[3][1], w3, xb);
        }
        __syncthreads();
    }
#pragma unroll
    for (int j = 0; j < 4; j++) {
        int n = n0 + ty * 4 + j;
        float bb = fcb[n];
        float l0, l1, l2, l3;
        asm("mov.b64 {%0, %1}, %2;" : "=f"(l0), "=f"(l1) : "l"(acc[j][0]));
        asm("mov.b64 {%0, %1}, %2;" : "=f"(l2), "=f"(l3) : "l"(acc[j][1]));
        int b = tx * 4;
        d_logits[((size_t)t * BATCH + b + 0) * DOUT + n] = l0 + bb;
        d_logits[((size_t)t * BATCH + b + 1) * DOUT + n] = l1 + bb;
        d_logits[((size_t)t * BATCH + b + 2) * DOUT + n] = l2 + bb;
        d_logits[((size_t)t * BATCH + b + 3) * DOUT + n] = l3 + bb;
    }
}

// ---------------- softmax over last dim (256), one warp per (t,b) row ----------------
__global__ __launch_bounds__(256) void softmax_kernel(float* __restrict__ out) {
    int row = blockIdx.x * 8 + (threadIdx.x >> 5);
    if (row >= TSTEPS * BATCH) return;
    int lane = threadIdx.x & 31;
    const float* lp = d_logits + (size_t)row * DOUT;
    float v[8];
    float m = -INFINITY;
#pragma unroll
    for (int i = 0; i < 8; i++) { v[i] = lp[lane + 32 * i]; m = fmaxf(m, v[i]); }
#pragma unroll
    for (int o = 16; o > 0; o >>= 1) m = fmaxf(m, __shfl_xor_sync(0xffffffffu, m, o));
    float s = 0.0f;
#pragma unroll
    for (int i = 0; i < 8; i++) { v[i] = expf(v[i] - m); s += v[i]; }
#pragma unroll
    for (int o = 16; o > 0; o >>= 1) s += __shfl_xor_sync(0xffffffffu, s, o);
    float inv = 1.0f / s;
    float* op = out + (size_t)row * DOUT;
#pragma unroll
    for (int i = 0; i < 8; i++) op[lane + 32 * i] = v[i] * inv;
}

// ---------------- launch ----------------
extern "C" void kernel_launch(void* const* d_in, const int* in_sizes, int n_in,
                              void* d_out, int out_size) {
    const float* x      = (const float*)d_in[0];
    const float* target = (const float*)d_in[1];
    const float* h0     = (const float*)d_in[2];
    const float* c0     = (const float*)d_in[3];
    const float* eWih   = (const float*)d_in[4];
    const float* eWhh   = (const float*)d_in[5];
    const float* eb     = (const float*)d_in[6];
    const float* dWih   = (const float*)d_in[7];
    const float* dWhh   = (const float*)d_in[8];
    const float* db     = (const float*)d_in[9];
    const float* fcW    = (const float*)d_in[10];
    const float* fcb    = (const float*)d_in[11];
    float* out = (float*)d_out;

    const int smem_recur = (16 * 256 + 256 * 64) * 8;   // 163840 B
    cudaFuncSetAttribute(recur_kernel, cudaFuncAttributeMaxDynamicSharedMemorySize, smem_recur);

    init_state<<<128, 256>>>(h0, c0);
    proj_kernel<<<dim3(32, TSTEPS), 256>>>(x, eWih, eb, 0);
    recur_kernel<<<NBLK, 256, smem_recur>>>(eWhh, 0);
    proj_kernel<<<dim3(32, TSTEPS), 256>>>(target, dWih, db, 1);
    recur_kernel<<<NBLK, 256, smem_recur>>>(dWhh, 1);
    fc_kernel<<<dim3(4, TSTEPS), 256>>>(fcW, fcb);
    softmax_kernel<<<(TSTEPS * BATCH + 7) / 8, 256>>>(out);
}

// round 2
// speedup vs baseline: 1.0004x; 1.0004x over previous
#include <cuda_runtime.h>
#include <math.h>

#define TSTEPS 512
#define BATCH  64
#define DIN    256
#define HID    512
#define DOUT   256
#define G4H    2048
#define NBLK   128

typedef unsigned long long ull;

// ---------------- scratch (module-scope __device__ arrays: no allocation) ----------------
__device__ float d_Genc[(size_t)TSTEPS * G4H * BATCH];    // [t][gate*H+u][b]  (268 MB)
__device__ float d_Gdec[(size_t)TSTEPS * G4H * BATCH];    // (268 MB)
__device__ float d_hbuf[2][HID * BATCH];                  // packed pairs: [(u>>1)*B + b]*2 + (u&1)
__device__ float d_cbuf[HID * BATCH];                     // [u][b]
__device__ float d_hs[(size_t)TSTEPS * HID * BATCH];      // [t][u][b]   (64 MB)
__device__ float d_logits[(size_t)TSTEPS * BATCH * DOUT]; // [t][b][n]   (32 MB)
__device__ unsigned g_count;
__device__ volatile unsigned g_gen;

// ---------------- f32x2 helpers ----------------
__device__ __forceinline__ void fma2(ull& a, ull x, ull y) {
    asm("fma.rn.f32x2 %0, %1, %2, %3;" : "=l"(a) : "l"(x), "l"(y), "l"(a));
}
__device__ __forceinline__ ull pack2(float lo, float hi) {
    ull r; asm("mov.b64 %0, {%1, %2};" : "=l"(r) : "f"(lo), "f"(hi)); return r;
}
__device__ __forceinline__ float sum2(ull v) {
    float lo, hi; asm("mov.b64 {%0, %1}, %2;" : "=f"(lo), "=f"(hi) : "l"(v));
    return lo + hi;
}
__device__ __forceinline__ float sigmoidf_(float x) { return 1.0f / (1.0f + expf(-x)); }

// ---------------- init: pack initial h (pair-interleaved) and c ----------------
__global__ __launch_bounds__(256) void init_state(const float* __restrict__ h0,
                                                  const float* __restrict__ c0) {
    int i = blockIdx.x * blockDim.x + threadIdx.x;   // 0..32767
    if (i >= HID * BATCH) return;
    int b = i >> 9;           // h0 layout [1][B][H] -> element (b,u) at b*H+u
    int u = i & 511;
    d_hbuf[0][((u >> 1) * BATCH + b) * 2 + (u & 1)] = h0[i];
    d_cbuf[u * BATCH + b] = c0[i];
}

// ---------------- input projection GEMM: G[t][n][b] = sum_k W[n][k]*X[t'][b][k] + bias[n] ----
// which = 0: enc (X = x, t' = t);  which = 1: dec (X = target, t' = t-1; t==0 -> zeros)
__global__ __launch_bounds__(256) void proj_kernel(const float* __restrict__ X,
                                                   const float* __restrict__ W,
                                                   const float* __restrict__ bias,
                                                   int which) {
    __shared__ ull   Ws2[64][33];   // duplicated (w,w) pairs
    __shared__ float Xs[32][68];    // [k][b], padded (row stride 272B, 16B aligned)

    float* __restrict__ Gout = which ? d_Gdec : d_Genc;
    int t  = blockIdx.y;
    int n0 = blockIdx.x * 64;
    int tid = threadIdx.x;
    int tx = tid & 15, ty = tid >> 4;           // tx -> 4 b's, ty -> 4 n's
    bool zero_x = (which && t == 0);
    const float* Xt = X + ((size_t)(t - which) * BATCH) * DIN;

    ull acc[4][2];
#pragma unroll
    for (int j = 0; j < 4; j++) { acc[j][0] = 0ull; acc[j][1] = 0ull; }

    int ldn = tid >> 2;               // 0..63
    int ldk = (tid & 3) * 8;          // 0,8,16,24

    for (int k0 = 0; k0 < DIN; k0 += 32) {
        // weights: 64 rows x 32 k, duplicated into ull pairs
        {
            const float4* src = (const float4*)(W + (size_t)(n0 + ldn) * DIN + k0 + ldk);
            float4 a = src[0], c = src[1];
            Ws2[ldn][ldk + 0] = pack2(a.x, a.x);
            Ws2[ldn][ldk + 1] = pack2(a.y, a.y);
            Ws2[ldn][ldk + 2] = pack2(a.z, a.z);
            Ws2[ldn][ldk + 3] = pack2(a.w, a.w);
            Ws2[ldn][ldk + 4] = pack2(c.x, c.x);
            Ws2[ldn][ldk + 5] = pack2(c.y, c.y);
            Ws2[ldn][ldk + 6] = pack2(c.z, c.z);
            Ws2[ldn][ldk + 7] = pack2(c.w, c.w);
        }
        // activations: transpose-load X[t'][b][k] -> Xs[k][b]
        if (zero_x) {
#pragma unroll
            for (int i = 0; i < 8; i++) Xs[ldk + i][ldn] = 0.0f;
        } else {
            const float4* src = (const float4*)(Xt + (size_t)ldn * DIN + k0 + ldk);
            float4 a = src[0], c = src[1];
            Xs[ldk + 0][ldn] = a.x; Xs[ldk + 1][ldn] = a.y;
            Xs[ldk + 2][ldn] = a.z; Xs[ldk + 3][ldn] = a.w;
            Xs[ldk + 4][ldn] = c.x; Xs[ldk + 5][ldn] = c.y;
            Xs[ldk + 6][ldn] = c.z; Xs[ldk + 7][ldn] = c.w;
        }
        __syncthreads();
#pragma unroll 8
        for (int k = 0; k < 32; k++) {
            ull xa = *(const ull*)&Xs[k][tx * 4];
            ull xb = *(const ull*)&Xs[k][tx * 4 + 2];
            ull w0 = Ws2[ty * 4 + 0][k];
            ull w1 = Ws2[ty * 4 + 1][k];
            ull w2 = Ws2[ty * 4 + 2][k];
            ull w3 = Ws2[ty * 4 + 3][k];
            fma2(acc[0][0], w0, xa); fma2(acc[0][1], w0, xb);
            fma2(acc[1][0], w1, xa); fma2(acc[1][1], w1, xb);
            fma2(acc[2][0], w2, xa); fma2(acc[2][1], w2, xb);
            fma2(acc[3][0], w3, xa); fma2(acc[3][1], w3, xb);
        }
        __syncthreads();
    }
#pragma unroll
    for (int j = 0; j < 4; j++) {
        int n = n0 + ty * 4 + j;
        float bb = bias[n];
        float l0, l1, l2, l3;
        asm("mov.b64 {%0, %1}, %2;" : "=f"(l0), "=f"(l1) : "l"(acc[j][0]));
        asm("mov.b64 {%0, %1}, %2;" : "=f"(l2), "=f"(l3) : "l"(acc[j][1]));
        float4 o = make_float4(l0 + bb, l1 + bb, l2 + bb, l3 + bb);
        *(float4*)(Gout + ((size_t)t * G4H + n) * BATCH + tx * 4) = o;
    }
}

// ---------------- software grid barrier (all NBLK blocks co-resident) ----------------
__device__ __forceinline__ void grid_sync() {
    __syncthreads();
    if (threadIdx.x == 0) {
        __threadfence();
        unsigned target = g_gen + 1;          // read BEFORE arriving
        unsigned a = atomicAdd(&g_count, 1u);
        if (a == NBLK - 1) {
            atomicExch(&g_count, 0u);
            __threadfence();
            g_gen = target;
        } else {
            while (g_gen != target) { }
        }
        __threadfence();
    }
    __syncthreads();
}

// ---------------- persistent recurrent LSTM kernel ----------------
// which = 0: encoder (reads d_Genc, no hs); which = 1: decoder (reads d_Gdec, writes d_hs)
__global__ __launch_bounds__(256) void recur_kernel(const float* __restrict__ Whh, int which) {
    extern __shared__ ull sm[];
    ull* w2 = sm;                 // [16 rows][256 pairs]  (32 KB)
    ull* h2 = sm + 16 * 256;      // [256 pairs][64 b]     (128 KB)

    const float* __restrict__ G = which ? d_Gdec : d_Genc;
    int tid = threadIdx.x;
    int b = tid & 63, ul = tid >> 6;
    int u0 = blockIdx.x * 4;
    int u = u0 + ul;

    // load this block's 16 Whh rows (4 units x 4 gates) as f32x2 pairs
    for (int idx = tid; idx < 16 * 256; idx += 256) {
        int r = idx >> 8, kk = idx & 255;
        int g = r >> 2, uu = r & 3;
        const float* wr = Whh + ((size_t)(g * HID + u0 + uu)) * HID + kk * 2;
        w2[idx] = *(const ull*)wr;
    }

    float c = d_cbuf[u * BATCH + b];
    const ulonglong2* wi2 = (const ulonglong2*)(w2 + (0 * 4 + ul) * 256);
    const ulonglong2* wf2 = (const ulonglong2*)(w2 + (1 * 4 + ul) * 256);
    const ulonglong2* wg2 = (const ulonglong2*)(w2 + (2 * 4 + ul) * 256);
    const ulonglong2* wo2 = (const ulonglong2*)(w2 + (3 * 4 + ul) * 256);

    for (int t = 0; t < TSTEPS; t++) {
        grid_sync();                                     // previous step's h is published
        // stage h (128 KB) into smem
        const float4* src = (const float4*)d_hbuf[t & 1];
        float4* dst = (float4*)h2;
#pragma unroll
        for (int i = 0; i < 32; i++) dst[tid + i * 256] = src[tid + i * 256];
        // prefetch this thread's 4 precomputed gate inputs (x-proj + bias)
        size_t gb = ((size_t)t * G4H + u) * BATCH + b;
        float pi = G[gb];
        float pf = G[gb + (size_t)512 * BATCH];
        float pg = G[gb + (size_t)1024 * BATCH];
        float po = G[gb + (size_t)1536 * BATCH];
        __syncthreads();

        ull ai = 0ull, af = 0ull, ag = 0ull, ao = 0ull;
        const ull* hp = h2 + b;
#pragma unroll 4
        for (int kk2 = 0; kk2 < 128; kk2++) {
            ull h0v = hp[kk2 * 128];
            ull h1v = hp[kk2 * 128 + 64];
            ulonglong2 wiv = wi2[kk2], wfv = wf2[kk2], wgv = wg2[kk2], wov = wo2[kk2];
            fma2(ai, wiv.x, h0v); fma2(ai, wiv.y, h1v);
            fma2(af, wfv.x, h0v); fma2(af, wfv.y, h1v);
            fma2(ag, wgv.x, h0v); fma2(ag, wgv.y, h1v);
            fma2(ao, wov.x, h0v); fma2(ao, wov.y, h1v);
        }
        float gi = sum2(ai) + pi;
        float gf = sum2(af) + pf;
        float gg = sum2(ag) + pg;
        float go = sum2(ao) + po;
        float iv = sigmoidf_(gi);
        float fv = sigmoidf_(gf);
        float gv = tanhf(gg);
        float ov = sigmoidf_(go);
        c = fv * c + iv * gv;
        float h = ov * tanhf(c);

        float* ho = d_hbuf[(t + 1) & 1];
        ho[((u >> 1) * BATCH + b) * 2 + (u & 1)] = h;
        if (which) d_hs[((size_t)t * HID + u) * BATCH + b] = h;
    }
    d_cbuf[u * BATCH + b] = c;   // hand c to the decoder kernel
}

// ---------------- FC: logits[t][b][n] = hs[t][b][:] . fcW[n][:] + fcb[n] ----------------
__global__ __launch_bounds__(256) void fc_kernel(const float* __restrict__ fcW,
                                                 const float* __restrict__ fcb) {
    __shared__ ull   Ws2[64][33];
    __shared__ float Hs[32][68];

    int t  = blockIdx.y;
    int n0 = blockIdx.x * 64;
    int tid = threadIdx.x;
    int tx = tid & 15, ty = tid >> 4;

    ull acc[4][2];
#pragma unroll
    for (int j = 0; j < 4; j++) { acc[j][0] = 0ull; acc[j][1] = 0ull; }

    int ldn = tid >> 2;
    int ldk = (tid & 3) * 8;

    for (int k0 = 0; k0 < HID; k0 += 32) {
        {
            const float4* src = (const float4*)(fcW + (size_t)(n0 + ldn) * HID + k0 + ldk);
            float4 a = src[0], c = src[1];
            Ws2[ldn][ldk + 0] = pack2(a.x, a.x);
            Ws2[ldn][ldk + 1] = pack2(a.y, a.y);
            Ws2[ldn][ldk + 2] = pack2(a.z, a.z);
            Ws2[ldn][ldk + 3] = pack2(a.w, a.w);
            Ws2[ldn][ldk + 4] = pack2(c.x, c.x);
            Ws2[ldn][ldk + 5] = pack2(c.y, c.y);
            Ws2[ldn][ldk + 6] = pack2(c.z, c.z);
            Ws2[ldn][ldk + 7] = pack2(c.w, c.w);
        }
        {
            // hs is already [t][k][b]: straight copy of a 32x64 chunk
            const float4* src = (const float4*)(d_hs + ((size_t)t * HID + k0) * BATCH);
#pragma unroll
            for (int i = 0; i < 2; i++) {
                int fi = tid * 2 + i;                 // float4 index within 2048 floats
                float4 v = src[fi];
                int k = fi >> 4, cb = (fi & 15) * 4;
                Hs[k][cb + 0] = v.x; Hs[k][cb + 1] = v.y;
                Hs[k][cb + 2] = v.z; Hs[k][cb + 3] = v.w;
            }
        }
        __syncthreads();
#pragma unroll 8
        for (int k = 0; k < 32; k++) {
            ull xa = *(const ull*)&Hs[k][tx * 4];
            ull xb = *(const ull*)&Hs[k][tx * 4 + 2];
            ull w0 = Ws2[ty * 4 + 0][k];
            ull w1 = Ws2[ty * 4 + 1][k];
            ull w2v = Ws2[ty * 4 + 2][k];
            ull w3 = Ws2[ty * 4 + 3][k];
            fma2(acc[0][0], w0, xa);  fma2(acc[0][1], w0, xb);
            fma2(acc[1][0], w1, xa);  fma2(acc[1][1], w1, xb);
            fma2(acc[2][0], w2v, xa); fma2(acc[2][1], w2v, xb);
            fma2(acc[3][0], w3, xa);  fma2(acc[3][1], w3, xb);
        }
        __syncthreads();
    }
#pragma unroll
    for (int j = 0; j < 4; j++) {
        int n = n0 + ty * 4 + j;
        float bb = fcb[n];
        float l0, l1, l2, l3;
        asm("mov.b64 {%0, %1}, %2;" : "=f"(l0), "=f"(l1) : "l"(acc[j][0]));
        asm("mov.b64 {%0, %1}, %2;" : "=f"(l2), "=f"(l3) : "l"(acc[j][1]));
        int b = tx * 4;
        d_logits[((size_t)t * BATCH + b + 0) * DOUT + n] = l0 + bb;
        d_logits[((size_t)t * BATCH + b + 1) * DOUT + n] = l1 + bb;
        d_logits[((size_t)t * BATCH + b + 2) * DOUT + n] = l2 + bb;
        d_logits[((size_t)t * BATCH + b + 3) * DOUT + n] = l3 + bb;
    }
}

// ---------------- softmax over last dim (256), one warp per (t,b) row ----------------
__global__ __launch_bounds__(256) void softmax_kernel(float* __restrict__ out) {
    int row = blockIdx.x * 8 + (threadIdx.x >> 5);
    if (row >= TSTEPS * BATCH) return;
    int lane = threadIdx.x & 31;
    const float* lp = d_logits + (size_t)row * DOUT;
    float v[8];
    float m = -INFINITY;
#pragma unroll
    for (int i = 0; i < 8; i++) { v[i] = lp[lane + 32 * i]; m = fmaxf(m, v[i]); }
#pragma unroll
    for (int o = 16; o > 0; o >>= 1) m = fmaxf(m, __shfl_xor_sync(0xffffffffu, m, o));
    float s = 0.0f;
#pragma unroll
    for (int i = 0; i < 8; i++) { v[i] = expf(v[i] - m); s += v[i]; }
#pragma unroll
    for (int o = 16; o > 0; o >>= 1) s += __shfl_xor_sync(0xffffffffu, s, o);
    float inv = 1.0f / s;
    float* op = out + (size_t)row * DOUT;
#pragma unroll
    for (int i = 0; i < 8; i++) op[lane + 32 * i] = v[i] * inv;
}

// ---------------- launch ----------------
extern "C" void kernel_launch(void* const* d_in, const int* in_sizes, int n_in,
                              void* d_out, int out_size) {
    const float* x      = (const float*)d_in[0];
    const float* target = (const float*)d_in[1];
    const float* h0     = (const float*)d_in[2];
    const float* c0     = (const float*)d_in[3];
    const float* eWih   = (const float*)d_in[4];
    const float* eWhh   = (const float*)d_in[5];
    const float* eb     = (const float*)d_in[6];
    const float* dWih   = (const float*)d_in[7];
    const float* dWhh   = (const float*)d_in[8];
    const float* db     = (const float*)d_in[9];
    const float* fcW    = (const float*)d_in[10];
    const float* fcb    = (const float*)d_in[11];
    float* out = (float*)d_out;

    const int smem_recur = (16 * 256 + 256 * 64) * 8;   // 163840 B
    cudaFuncSetAttribute(recur_kernel, cudaFuncAttributeMaxDynamicSharedMemorySize, smem_recur);

    init_state<<<128, 256>>>(h0, c0);
    proj_kernel<<<dim3(32, TSTEPS), 256>>>(x, eWih, eb, 0);
    recur_kernel<<<NBLK, 256, smem_recur>>>(eWhh, 0);
    proj_kernel<<<dim3(32, TSTEPS), 256>>>(target, dWih, db, 1);
    recur_kernel<<<NBLK, 256, smem_recur>>>(dWhh, 1);
    fc_kernel<<<dim3(4, TSTEPS), 256>>>(fcW, fcb);
    softmax_kernel<<<(TSTEPS * BATCH + 7) / 8, 256>>>(out);
}

// round 3
// speedup vs baseline: 1.1237x; 1.1233x over previous
#include <cuda_runtime.h>
#include <math.h>

#define TSTEPS 512
#define BATCH  64
#define DIN    256
#define HID    512
#define DOUT   256
#define G4H    2048
#define NBLK   128

typedef unsigned long long ull;

// ---------------- scratch ----------------
__device__ float d_Genc[(size_t)TSTEPS * G4H * BATCH];    // [t][gate*H+u][b]
__device__ float d_Gdec[(size_t)TSTEPS * G4H * BATCH];
__device__ float d_hbuf[2][HID * BATCH];                  // ull view: [kpair][b] = (h[2kp],h[2kp+1])
__device__ float d_cbuf[HID * BATCH];                     // [u][b]
__device__ float d_hs[(size_t)TSTEPS * HID * BATCH];      // [t][u][b]
__device__ float d_logits[(size_t)TSTEPS * BATCH * DOUT]; // [t][b][n]
__device__ unsigned g_count;
__device__ volatile unsigned g_gen;

// ---------------- helpers ----------------
__device__ __forceinline__ void fma2(ull& a, ull x, ull y) {
    asm("fma.rn.f32x2 %0, %1, %2, %3;" : "=l"(a) : "l"(x), "l"(y), "l"(a));
}
__device__ __forceinline__ ull pack2(float lo, float hi) {
    ull r; asm("mov.b64 %0, {%1, %2};" : "=l"(r) : "f"(lo), "f"(hi)); return r;
}
__device__ __forceinline__ float sum2(ull v) {
    float lo, hi; asm("mov.b64 {%0, %1}, %2;" : "=f"(lo), "=f"(hi) : "l"(v));
    return lo + hi;
}
__device__ __forceinline__ ull ldcg64(const ull* p) {
    ull v; asm volatile("ld.global.cg.u64 %0, [%1];" : "=l"(v) : "l"(p)); return v;
}
__device__ __forceinline__ float fsig(float x) {
    return __fdividef(1.0f, 1.0f + __expf(-x));
}
__device__ __forceinline__ float ftanh(float x) {
    float e = __expf(2.0f * x);                 // inf-safe: x>>0 -> 1, x<<0 -> -1
    return 1.0f - __fdividef(2.0f, e + 1.0f);
}

// ---------------- init: pack initial h (pair-interleaved) and c ----------------
__global__ __launch_bounds__(256) void init_state(const float* __restrict__ h0,
                                                  const float* __restrict__ c0) {
    int i = blockIdx.x * blockDim.x + threadIdx.x;
    if (i >= HID * BATCH) return;
    int b = i >> 9;                 // h0 layout [1][B][H]
    int u = i & 511;
    d_hbuf[0][((u >> 1) * BATCH + b) * 2 + (u & 1)] = h0[i];
    d_cbuf[u * BATCH + b] = c0[i];
}

// ---------------- unified register-blocked GEMM ----------------
// Out = X @ W^T + bias, per time step t = blockIdx.y.
// Tile: 128 n x 64 b, thread computes 8n x 4b with k-paired f32x2 accumulators.
// x_kb=0: X is [T][B][K] (proj; dec_shift shifts rows, t==0 row is zeros)
// x_kb=1: X is [T][K][B] (fc reading d_hs)
// out_bn=0: Out[t][n][b]; out_bn=1: Out[t][b][n]
__global__ __launch_bounds__(256, 2) void gemm_kernel(
    const float* __restrict__ X, const float* __restrict__ W,
    const float* __restrict__ bias, float* __restrict__ Out,
    int Ntot, int K, int kchunks, int dec_shift, int x_kb, int out_bn) {
    __shared__ ull Wt[16 * 130];   // [kk][n], pad 130 (even -> 16B aligned LDS.128)
    __shared__ ull Xt[16 * 66];    // [kk][b], pad 66

    int t  = blockIdx.y;
    int n0 = blockIdx.x * 128;
    int tid = threadIdx.x;
    int tx = tid & 15, ty = tid >> 4;     // tx -> 4 b's, ty -> 8 n's

    ull acc[8][4];
#pragma unroll
    for (int i = 0; i < 8; i++)
#pragma unroll
        for (int j = 0; j < 4; j++) acc[i][j] = 0ull;

    for (int ch = 0; ch < kchunks; ch++) {
        // stage weights: 128 n x 16 kpairs
        for (int idx = tid; idx < 2048; idx += 256) {
            int kk = idx & 15, n = idx >> 4;
            Wt[kk * 130 + n] = *(const ull*)(W + (size_t)(n0 + n) * K + ch * 32 + kk * 2);
        }
        // stage activations: 16 kpairs x 64 b
        if (x_kb) {
            for (int idx = tid; idx < 1024; idx += 256) {
                int b = idx & 63, kk = idx >> 6;
                int kg = ch * 32 + kk * 2;
                Xt[kk * 66 + b] = pack2(X[((size_t)t * K + kg) * 64 + b],
                                        X[((size_t)t * K + kg + 1) * 64 + b]);
            }
        } else {
            bool zero = (dec_shift && t == 0);
            int trow = t - dec_shift;
            for (int idx = tid; idx < 1024; idx += 256) {
                int kk = idx & 15, b = idx >> 4;
                Xt[kk * 66 + b] = zero ? 0ull
                    : *(const ull*)(X + ((size_t)trow * 64 + b) * K + ch * 32 + kk * 2);
            }
        }
        __syncthreads();
#pragma unroll
        for (int kk = 0; kk < 16; kk++) {
            ulonglong2 xv0 = *(const ulonglong2*)&Xt[kk * 66 + tx * 4];
            ulonglong2 xv1 = *(const ulonglong2*)&Xt[kk * 66 + tx * 4 + 2];
            ull xs0 = xv0.x, xs1 = xv0.y, xs2 = xv1.x, xs3 = xv1.y;
#pragma unroll
            for (int q = 0; q < 4; q++) {
                ulonglong2 wv = *(const ulonglong2*)&Wt[kk * 130 + ty * 8 + 2 * q];
                fma2(acc[2 * q][0], wv.x, xs0);
                fma2(acc[2 * q][1], wv.x, xs1);
                fma2(acc[2 * q][2], wv.x, xs2);
                fma2(acc[2 * q][3], wv.x, xs3);
                fma2(acc[2 * q + 1][0], wv.y, xs0);
                fma2(acc[2 * q + 1][1], wv.y, xs1);
                fma2(acc[2 * q + 1][2], wv.y, xs2);
                fma2(acc[2 * q + 1][3], wv.y, xs3);
            }
        }
        __syncthreads();
    }

    if (out_bn) {
        float bb[8];
#pragma unroll
        for (int i = 0; i < 8; i++) bb[i] = bias[n0 + ty * 8 + i];
#pragma unroll
        for (int j = 0; j < 4; j++) {
            int b = tx * 4 + j;
            float v[8];
#pragma unroll
            for (int i = 0; i < 8; i++) v[i] = sum2(acc[i][j]) + bb[i];
            float* op = Out + ((size_t)t * 64 + b) * Ntot + n0 + ty * 8;
            *(float4*)op       = make_float4(v[0], v[1], v[2], v[3]);
            *(float4*)(op + 4) = make_float4(v[4], v[5], v[6], v[7]);
        }
    } else {
#pragma unroll
        for (int i = 0; i < 8; i++) {
            int n = n0 + ty * 8 + i;
            float bb = bias[n];
            float4 o = make_float4(sum2(acc[i][0]) + bb, sum2(acc[i][1]) + bb,
                                   sum2(acc[i][2]) + bb, sum2(acc[i][3]) + bb);
            *(float4*)(Out + ((size_t)t * Ntot + n) * 64 + tx * 4) = o;
        }
    }
}

// ---------------- software grid barrier (128 co-resident blocks) ----------------
__device__ __forceinline__ void grid_sync() {
    __syncthreads();
    if (threadIdx.x == 0) {
        __threadfence();
        unsigned target = g_gen + 1;
        unsigned a = atomicAdd(&g_count, 1u);
        if (a == NBLK - 1) {
            atomicExch(&g_count, 0u);
            __threadfence();
            g_gen = target;
        } else {
            while (g_gen != target) { }
        }
        __threadfence();
    }
    __syncthreads();
}

// ---------------- persistent recurrent LSTM kernel (split-k across warps) ----------------
// Block owns 4 hidden units (16 gate rows). Warp w reduces kpairs [32w, 32w+32),
// reading h directly from L2 (pipelined ld.global.cg). Partials reduced via smem;
// epilogue thread (ul,b) owns c in registers.
__global__ __launch_bounds__(256) void recur_kernel(const float* __restrict__ Whh, int which) {
    extern __shared__ ull sm[];
    ull* ws  = sm;            // [kp][r]: kp*16 + r   (4096 ull = 32 KB)
    ull* red = sm + 4096;     // [(r*64+b)*9 + w]     (9216 ull = 72 KB)

    const float* __restrict__ G = which ? d_Gdec : d_Genc;
    int tid = threadIdx.x;
    int w = tid >> 5, l = tid & 31;        // FMA-phase mapping
    int ul = tid >> 6, b = tid & 63;       // epilogue mapping
    int u0 = blockIdx.x * 4;
    int u = u0 + ul;

    // load this block's 16 Whh rows, layout [kpair][row] (row = gate*4 + unit)
    for (int idx = tid; idx < 4096; idx += 256) {
        int kp = idx >> 4, r = idx & 15;
        int g = r >> 2, uu = r & 3;
        ws[idx] = *(const ull*)(Whh + ((size_t)(g * HID + u0 + uu)) * HID + kp * 2);
    }
    float c = d_cbuf[u * BATCH + b];
    int kbase = w * 32;

    for (int t = 0; t < TSTEPS; t++) {
        // prefetch precomputed x-projection gates (overlaps the barrier wait)
        size_t gb = ((size_t)t * G4H + u) * BATCH + b;
        float pi = G[gb];
        float pf = G[gb + (size_t)512 * 64];
        float pg = G[gb + (size_t)1024 * 64];
        float po = G[gb + (size_t)1536 * 64];

        grid_sync();                                     // previous h published

        const ull* hsrc = (const ull*)d_hbuf[t & 1];
        ull acc[16][2];
#pragma unroll
        for (int r = 0; r < 16; r++) { acc[r][0] = 0ull; acc[r][1] = 0ull; }

        ull buf[2][4][2];
#pragma unroll
        for (int i = 0; i < 4; i++) {
            buf[0][i][0] = ldcg64(hsrc + (kbase + i) * 64 + l);
            buf[0][i][1] = ldcg64(hsrc + (kbase + i) * 64 + 32 + l);
        }
#pragma unroll
        for (int ch = 0; ch < 8; ch++) {
            int cur = ch & 1, nxt = cur ^ 1;
            if (ch < 7) {
#pragma unroll
                for (int i = 0; i < 4; i++) {
                    int kp = kbase + (ch + 1) * 4 + i;
                    buf[nxt][i][0] = ldcg64(hsrc + kp * 64 + l);
                    buf[nxt][i][1] = ldcg64(hsrc + kp * 64 + 32 + l);
                }
            }
#pragma unroll
            for (int i = 0; i < 4; i++) {
                const ulonglong2* wp = (const ulonglong2*)(ws + (size_t)(kbase + ch * 4 + i) * 16);
                ull h0 = buf[cur][i][0], h1 = buf[cur][i][1];
#pragma unroll
                for (int rp = 0; rp < 8; rp++) {
                    ulonglong2 wv = wp[rp];
                    fma2(acc[2 * rp][0], wv.x, h0);
                    fma2(acc[2 * rp][1], wv.x, h1);
                    fma2(acc[2 * rp + 1][0], wv.y, h0);
                    fma2(acc[2 * rp + 1][1], wv.y, h1);
                }
            }
        }
        // store partials (pad-9 to keep bank conflicts at 2-way)
#pragma unroll
        for (int r = 0; r < 16; r++) {
            red[(size_t)(r * 64 + l) * 9 + w]      = acc[r][0];
            red[(size_t)(r * 64 + 32 + l) * 9 + w] = acc[r][1];
        }
        __syncthreads();

        // epilogue: thread (ul, b) reduces 8 warp-partials per gate
        float gate[4];
#pragma unroll
        for (int g = 0; g < 4; g++) {
            int r = g * 4 + ul;
            const ull* rp_ = red + (size_t)(r * 64 + b) * 9;
            float s = 0.0f;
#pragma unroll
            for (int w8 = 0; w8 < 8; w8++) s += sum2(rp_[w8]);
            gate[g] = s;
        }
        float iv = fsig(gate[0] + pi);
        float fv = fsig(gate[1] + pf);
        float gv = ftanh(gate[2] + pg);
        float ov = fsig(gate[3] + po);
        c = fv * c + iv * gv;
        float h = ov * ftanh(c);

        d_hbuf[(t + 1) & 1][((u >> 1) * 64 + b) * 2 + (u & 1)] = h;
        if (which) d_hs[((size_t)t * HID + u) * 64 + b] = h;
        // red reuse + h publication protected by next iteration's grid_sync
    }
    d_cbuf[u * 64 + b] = c;      // encoder -> decoder handoff
}

// ---------------- softmax over last dim (256), one warp per (t,b) row ----------------
__global__ __launch_bounds__(256) void softmax_kernel(float* __restrict__ out) {
    int row = blockIdx.x * 8 + (threadIdx.x >> 5);
    if (row >= TSTEPS * BATCH) return;
    int lane = threadIdx.x & 31;
    const float* lp = d_logits + (size_t)row * DOUT;
    float v[8];
    float m = -INFINITY;
#pragma unroll
    for (int i = 0; i < 8; i++) { v[i] = lp[lane + 32 * i]; m = fmaxf(m, v[i]); }
#pragma unroll
    for (int o = 16; o > 0; o >>= 1) m = fmaxf(m, __shfl_xor_sync(0xffffffffu, m, o));
    float s = 0.0f;
#pragma unroll
    for (int i = 0; i < 8; i++) { v[i] = expf(v[i] - m); s += v[i]; }
#pragma unroll
    for (int o = 16; o > 0; o >>= 1) s += __shfl_xor_sync(0xffffffffu, s, o);
    float inv = 1.0f / s;
    float* op = out + (size_t)row * DOUT;
#pragma unroll
    for (int i = 0; i < 8; i++) op[lane + 32 * i] = v[i] * inv;
}

// ---------------- launch ----------------
extern "C" void kernel_launch(void* const* d_in, const int* in_sizes, int n_in,
                              void* d_out, int out_size) {
    const float* x      = (const float*)d_in[0];
    const float* target = (const float*)d_in[1];
    const float* h0     = (const float*)d_in[2];
    const float* c0     = (const float*)d_in[3];
    const float* eWih   = (const float*)d_in[4];
    const float* eWhh   = (const float*)d_in[5];
    const float* eb     = (const float*)d_in[6];
    const float* dWih   = (const float*)d_in[7];
    const float* dWhh   = (const float*)d_in[8];
    const float* db     = (const float*)d_in[9];
    const float* fcW    = (const float*)d_in[10];
    const float* fcb    = (const float*)d_in[11];
    float* out = (float*)d_out;

    const int smem_recur = (4096 + 9216) * 8;   // 106496 B
    cudaFuncSetAttribute(recur_kernel, cudaFuncAttributeMaxDynamicSharedMemorySize, smem_recur);

    init_state<<<128, 256>>>(h0, c0);

    float* genc; cudaGetSymbolAddress((void**)&genc, d_Genc);
    float* gdec; cudaGetSymbolAddress((void**)&gdec, d_Gdec);
    float* ghs;  cudaGetSymbolAddress((void**)&ghs,  d_hs);
    float* glog; cudaGetSymbolAddress((void**)&glog, d_logits);

    // encoder + decoder input projections (independent of the recurrences)
    gemm_kernel<<<dim3(16, TSTEPS), 256>>>(x,      eWih, eb, genc, G4H, DIN, DIN / 32, 0, 0, 0);
    gemm_kernel<<<dim3(16, TSTEPS), 256>>>(target, dWih, db, gdec, G4H, DOUT, DOUT / 32, 1, 0, 0);

    recur_kernel<<<NBLK, 256, smem_recur>>>(eWhh, 0);
    recur_kernel<<<NBLK, 256, smem_recur>>>(dWhh, 1);

    gemm_kernel<<<dim3(2, TSTEPS), 256>>>(ghs, fcW, fcb, glog, DOUT, HID, HID / 32, 0, 1, 1);
    softmax_kernel<<<(TSTEPS * BATCH + 7) / 8, 256>>>(out);
}